// round 6
// baseline (speedup 1.0000x reference)
#include <cuda_runtime.h>
#include <math.h>

#define NY 1024
#define NX 1024
#define NXP 1026
#define NSTEPS 64
#define NPTS (NY*NX)
#define INV 0.02f

__device__ float g_H0[NPTS];
__device__ float g_H1[NPTS];
__device__ float g_smb[NPTS];
__device__ int g_maxDbits[NSTEPS];
__device__ unsigned g_arrive;
__device__ unsigned g_done[256 * 8];

static __device__ __forceinline__ unsigned ld_acq(const unsigned* p) {
    unsigned v;
    asm volatile("ld.acquire.gpu.global.u32 %0, [%1];" : "=r"(v) : "l"(p) : "memory");
    return v;
}
static __device__ __forceinline__ void red_add_rel(unsigned* p, unsigned v) {
    asm volatile("red.release.gpu.global.add.u32 [%0], %1;" :: "l"(p), "r"(v) : "memory");
}

static __device__ __forceinline__ float smb_of(float Zs, float precip, float mask,
                                               float tma_low, float tmj_low) {
    float T_ma = tma_low - 0.0065f * Zs;
    float T_mj = tmj_low - 0.0065f * Zs;
    float acc = precip * (T_ma < 0.0f ? 1.0f : 0.0f);
    float abl = 0.5f * fmaxf(T_mj, 0.0f);
    return (acc - abl) * mask;
}

__global__ void k_reset() {
    int t = threadIdx.x;
    if (t == 0) g_arrive = 0u;
    if (t < NSTEPS) g_maxDbits[t] = 0;
    for (int k = t; k < 256 * 8; k += blockDim.x) g_done[k] = 0u;
}

__global__ void __launch_bounds__(1024, 1)
k_persist(const float* __restrict__ precip,
          const float* __restrict__ tma_p,
          const float* __restrict__ tmj_p,
          const float* __restrict__ Ztopo,
          const float* __restrict__ mask,
          float* __restrict__ out) {
    extern __shared__ float sm[];
    float* sZ  = sm;                    // 3 * NXP  (z of read state, rows ring, padded)
    float* sHw = sZ  + 3 * NXP;         // 3 * NXP  (Hn rows ring, padded)
    float* sZn = sHw + 3 * NXP;         // 3 * NXP  (Zn rows ring, padded)
    float* sDb = sZn + 3 * NXP;         // 8 * NX   (persistent D band: slot = row-(r0-1))
    __shared__ float wred[32];

    const int i = threadIdx.x;          // column 0..1023
    const int si = i + 1;               // padded column
    const int il = (i == 0) ? 0 : i - 1;
    const int nb = gridDim.x;
    const int bid = blockIdx.x;
    const int lane = i & 31, wid = i >> 5;
    const unsigned FULL = 0xFFFFFFFFu;
    const bool iIn = (i > 0) && (i < NX - 1);

    int base = NY / nb, rem = NY % nb;
    int r0 = bid * base + (bid < rem ? bid : rem);
    int r1 = r0 + base + (bid < rem ? 1 : 0);
    const int band = r1 - r0;           // <= 7

    const float tma = tma_p[0], tmj = tmj_p[0];
    const float CFACT = (float)(1e-17 * 8927.1 * 8927.1 * 8927.1);

    // ---- one-time init ----
    if (i < 3) {
        sZ [i * NXP] = 0.f; sZ [i * NXP + NXP - 1] = 0.f;
        sHw[i * NXP] = 0.f; sHw[i * NXP + NXP - 1] = 0.f;
        sZn[i * NXP] = 0.f; sZn[i * NXP + NXP - 1] = 0.f;
    }
    #pragma unroll
    for (int k = 0; k < 8; k++) sDb[k * NX + i] = 1e-10f;
    for (int j = r0; j < r1; j++) {
        int idx = j * NX + i;
        g_H0[idx] = 0.0f;
        g_smb[idx] = smb_of(Ztopo[idx], precip[idx], mask[idx], tma, tmj);
    }
    unsigned target = nb;
    __syncthreads();
    if (i == 0) { red_add_rel(&g_arrive, 1u); while (ld_acq(&g_arrive) < target) __nanosleep(20); }
    __syncthreads();
    target += nb;

    float time = 0.0f, tlast = 0.0f;

    for (int s = 0; s < NSTEPS; s++) {
        const float* Hr = (s & 1) ? g_H1 : g_H0;
        float*       Hw = (s & 1) ? g_H0 : g_H1;

        float maxD = (s == 0) ? 1e-10f : __int_as_float(__ldcg(&g_maxDbits[s]));
        float dt = fminf(2500.0f / (2.7f * maxD), 0.5f);
        if (!(time < 32.0f)) dt = 0.0f;
        float tnew = time + dt;
        bool  upd  = (tnew - tlast) >= 5.0f;
        const bool last = (s == NSTEPS - 1);

        // ---- prologue: stage z row r0, load zU / D row r0-1 regs ----
        int idx = r0 * NX + i;
        float zU = 0.f;
        if (r0 > 0) zU = Ztopo[idx - NX] + __ldcg(&Hr[idx - NX]);
        float hC  = Hr[idx];
        float ZtC = Ztopo[idx];
        float zC  = ZtC + hC;
        sZ[(r0 % 3) * NXP + si] = zC;
        float Dmm = sDb[il], Dm0 = sDb[i];       // slot 0 = D row r0-1
        float hw_prev = 0.f, zn_prev = 0.f;
        float lmax = 0.f;
        __syncthreads();

        // ---- fused sweep: H row j, then D(next) row j-1 ----
        for (int j = r0; j < r1; j++, idx += NX) {
            const int c = j % 3, n = (j + 1) % 3, p = (j + 2) % 3;
            const int slot = j - r0 + 1;

            // phase 1: H update of row j
            const float* hp = &Hr[idx + NX];
            float h_next  = 0.f, zt_next = 0.f;
            if (j + 1 < NY) {
                h_next  = (j + 1 < r1) ? *hp : __ldcg(hp);
                zt_next = Ztopo[idx + NX];
            }
            float z_next = zt_next + h_next;
            float zL = sZ[c * NXP + si - 1];
            float zR = sZ[c * NXP + si + 1];
            float D00 = sDb[slot * NX + i];
            float D0m = sDb[slot * NX + il];
            float smbv = g_smb[idx];

            float Hn = hC;
            if (iIn && (j > 0) && (j < NY - 1)) {
                float qxr = -(0.5f * (Dm0 + D00)) * (zR - zC) * INV;
                float qxl = -(0.5f * (Dmm + D0m)) * (zC - zL) * INV;
                float qyd = -(0.5f * (D0m + D00)) * (z_next - zC) * INV;
                float qyu = -(0.5f * (Dmm + Dm0)) * (zC - zU) * INV;
                float dHdt = -((qxr - qxl) * INV + (qyd - qyu) * INV);
                Hn = hC + dt * (dHdt + smbv);
            }
            Hn = fmaxf(Hn, 0.0f);
            Hw[idx] = Hn;
            float Zn = ZtC + Hn;

            // phase 2: stage rows
            sHw[c * NXP + si] = Hn;
            sZn[c * NXP + si] = Zn;
            sZ [n * NXP + si] = z_next;
            __syncthreads();

            // phase 3: D(next step) row j-1 (from Hn rows j-1, j)
            if (j > r0) {
                float h01 = sHw[p * NXP + si + 1], h11 = sHw[c * NXP + si + 1];
                float z01 = sZn[p * NXP + si + 1], z11 = sZn[c * NXP + si + 1];
                float H_avg = 0.25f * (((hw_prev + h11) + h01) + Hn);
                float sx = 0.5f * ((z01 - zn_prev) * INV + (z11 - Zn) * INV);
                float sy = 0.5f * ((Zn - zn_prev) * INV + (z11 - z01) * INV);
                float s2 = sx * sx + sy * sy + 1e-10f;
                float h2 = H_avg * H_avg;
                float D = CFACT * ((h2 * h2) * H_avg) * s2 + 1e-10f;
                if (i < NX - 1) {
                    sDb[(slot - 1) * NX + i] = D;
                    lmax = fmaxf(lmax, D);
                }
            }
            // rolls
            zU = zC; zC = z_next; hC = h_next; ZtC = zt_next;
            Dmm = D0m; Dm0 = D00;
            hw_prev = Hn; zn_prev = Zn;
        }

        if (last) {
            for (int j = r0; j < r1; j++) {
                int k = j * NX + i;
                out[k] = Hw[k];
            }
            break;
        }

        // ---- publish own band, overlap smb refresh with neighbor skew ----
        __syncthreads();
        if (i == 0) red_add_rel(&g_done[bid * 8], 1u);

        if (upd) {
            for (int j = r0; j < r1; j++) {
                int k = j * NX + i;
                float Hn = Hw[k];
                float Zn = Ztopo[k] + Hn;
                g_smb[k] = smb_of(Zn, precip[k], mask[k], tma, tmj);
            }
        }

        if (i == 0 && bid > 0)       { while (ld_acq(&g_done[(bid - 1) * 8]) < (unsigned)(s + 1)) __nanosleep(20); }
        if (i == 32 && bid < nb - 1) { while (ld_acq(&g_done[(bid + 1) * 8]) < (unsigned)(s + 1)) __nanosleep(20); }
        __syncthreads();

        // ---- boundary D rows via global loads ----
        if (r0 >= 1 && i < NX - 1) {            // D row r0-1 (needs neighbor row r0-1)
            int ia = (r0 - 1) * NX + i, ib = r0 * NX + i;
            float hA = __ldcg(&Hw[ia]), hAr = __ldcg(&Hw[ia + 1]);
            float hB = Hw[ib],          hBr = Hw[ib + 1];
            float z00 = Ztopo[ia] + hA, z01 = Ztopo[ia + 1] + hAr;
            float z10 = Ztopo[ib] + hB, z11 = Ztopo[ib + 1] + hBr;
            float H_avg = 0.25f * (((hA + hBr) + hAr) + hB);
            float sx = 0.5f * ((z01 - z00) * INV + (z11 - z10) * INV);
            float sy = 0.5f * ((z10 - z00) * INV + (z11 - z01) * INV);
            float s2 = sx * sx + sy * sy + 1e-10f;
            float h2 = H_avg * H_avg;
            float D = CFACT * ((h2 * h2) * H_avg) * s2 + 1e-10f;
            sDb[i] = D;
            lmax = fmaxf(lmax, D);
        }
        if (r1 <= NY - 1 && i < NX - 1) {       // D row r1-1 (needs neighbor row r1)
            int ia = (r1 - 1) * NX + i, ib = r1 * NX + i;
            float hA = Hw[ia],          hAr = Hw[ia + 1];
            float hB = __ldcg(&Hw[ib]), hBr = __ldcg(&Hw[ib + 1]);
            float z00 = Ztopo[ia] + hA, z01 = Ztopo[ia + 1] + hAr;
            float z10 = Ztopo[ib] + hB, z11 = Ztopo[ib + 1] + hBr;
            float H_avg = 0.25f * (((hA + hBr) + hAr) + hB);
            float sx = 0.5f * ((z01 - z00) * INV + (z11 - z10) * INV);
            float sy = 0.5f * ((z10 - z00) * INV + (z11 - z01) * INV);
            float s2 = sx * sx + sy * sy + 1e-10f;
            float h2 = H_avg * H_avg;
            float D = CFACT * ((h2 * h2) * H_avg) * s2 + 1e-10f;
            sDb[band * NX + i] = D;
            lmax = fmaxf(lmax, D);
        }

        // ---- max reduce -> slot s+1, then one global barrier ----
        #pragma unroll
        for (int o = 16; o > 0; o >>= 1)
            lmax = fmaxf(lmax, __shfl_xor_sync(FULL, lmax, o));
        if (lane == 0) wred[wid] = lmax;
        __syncthreads();
        if (wid == 0) {
            float m = wred[lane];
            #pragma unroll
            for (int o = 16; o > 0; o >>= 1)
                m = fmaxf(m, __shfl_xor_sync(FULL, m, o));
            if (lane == 0) atomicMax(&g_maxDbits[s + 1], __float_as_int(m));
        }
        __syncthreads();
        if (i == 0) { red_add_rel(&g_arrive, 1u); while (ld_acq(&g_arrive) < target) __nanosleep(20); }
        __syncthreads();
        target += nb;

        time = tnew;
        if (upd) tlast = tnew;
    }
}

extern "C" void kernel_launch(void* const* d_in, const int* in_sizes, int n_in,
                              void* d_out, int out_size) {
    const float* precip = (const float*)d_in[0];
    const float* tma_p  = (const float*)d_in[1];
    const float* tmj_p  = (const float*)d_in[2];
    const float* Ztopo  = (const float*)d_in[3];
    const float* mask   = (const float*)d_in[4];
    float* out = (float*)d_out;

    int dev = 0;
    cudaGetDevice(&dev);
    int sms = 0;
    cudaDeviceGetAttribute(&sms, cudaDevAttrMultiProcessorCount, dev);
    if (sms < 1) sms = 1;
    if (sms > 256) sms = 256;

    const int smem_bytes = (9 * NXP + 8 * NX) * (int)sizeof(float);
    cudaFuncSetAttribute(k_persist, cudaFuncAttributeMaxDynamicSharedMemorySize, smem_bytes);

    k_reset<<<1, 1024>>>();
    k_persist<<<sms, 1024, smem_bytes>>>(precip, tma_p, tmj_p, Ztopo, mask, out);
}

// round 7
// speedup vs baseline: 1.2233x; 1.2233x over previous
#include <cuda_runtime.h>
#include <math.h>

#define NY 1024
#define NX 1024
#define NXP 1026
#define NSTEPS 64
#define NPTS (NY*NX)
#define INV 0.02f

__device__ float g_H0[NPTS];
__device__ float g_H1[NPTS];
__device__ int g_maxDbits[NSTEPS];
__device__ unsigned g_arrive;
__device__ unsigned g_done[256 * 8];

static __device__ __forceinline__ unsigned ld_acq(const unsigned* p) {
    unsigned v;
    asm volatile("ld.acquire.gpu.global.u32 %0, [%1];" : "=r"(v) : "l"(p) : "memory");
    return v;
}
static __device__ __forceinline__ void red_add_rel(unsigned* p, unsigned v) {
    asm volatile("red.release.gpu.global.add.u32 [%0], %1;" :: "l"(p), "r"(v) : "memory");
}

static __device__ __forceinline__ float smb_of(float Zs, float precip, float mask,
                                               float tma_low, float tmj_low) {
    float T_ma = tma_low - 0.0065f * Zs;
    float T_mj = tmj_low - 0.0065f * Zs;
    float acc = precip * (T_ma < 0.0f ? 1.0f : 0.0f);
    float abl = 0.5f * fmaxf(T_mj, 0.0f);
    return (acc - abl) * mask;
}

__global__ void k_reset() {
    int t = threadIdx.x;
    if (t == 0) g_arrive = 0u;
    if (t < NSTEPS) g_maxDbits[t] = 0;
    for (int k = t; k < 256 * 8; k += blockDim.x) g_done[k] = 0u;
}

// phase 1+2 of one row: H update, global+ring staging, barrier.
// HEXPR: load of H(read) at row j+1; PRED: whether this row updates in j.
#define PHASE12(HEXPR, PRED)                                            \
    h_next  = (HEXPR);                                                  \
    zt_next = sZt[ztoff + si];                                          \
    z_next  = zt_next + h_next;                                         \
    {                                                                   \
        float zL = sZr[c + si - 1];                                     \
        float zR = sZr[c + si + 1];                                     \
        D00 = sDp[i]; D0m = sDp[il];                                    \
        float smbv = sSmb[smoff + i];                                   \
        float Hn_ = hC;                                                 \
        if (PRED) {                                                     \
            float qxr = -(0.5f * (Dm0 + D00)) * (zR - zC) * INV;        \
            float qxl = -(0.5f * (Dmm + D0m)) * (zC - zL) * INV;        \
            float qyd = -(0.5f * (D0m + D00)) * (z_next - zC) * INV;    \
            float qyu = -(0.5f * (Dmm + Dm0)) * (zC - zU) * INV;        \
            float dHdt = -((qxr - qxl) * INV + (qyd - qyu) * INV);      \
            Hn_ = hC + dt * (dHdt + smbv);                              \
        }                                                               \
        Hn = fmaxf(Hn_, 0.0f);                                          \
    }                                                                   \
    Hw[idx] = Hn;                                                       \
    Zn = ZtC + Hn;                                                      \
    sHwr[c + si] = Hn;                                                  \
    sZnr[c + si] = Zn;                                                  \
    sZr[n + si]  = z_next;                                              \
    __syncthreads();

// phase 3: D(next step) for row j-1 from Hn rows j-1, j (stores slot j-r0)
#define PHASE3                                                          \
    {                                                                   \
        float h01 = sHwr[p + si + 1], h11 = sHwr[c + si + 1];           \
        float z01 = sZnr[p + si + 1], z11 = sZnr[c + si + 1];           \
        float H_avg = 0.25f * (((hw_prev + h11) + h01) + Hn);           \
        float sx = 0.5f * ((z01 - zn_prev) * INV + (z11 - Zn) * INV);   \
        float sy = 0.5f * ((Zn - zn_prev) * INV + (z11 - z01) * INV);   \
        float s2 = sx * sx + sy * sy + 1e-10f;                          \
        float h2 = H_avg * H_avg;                                       \
        float Dv = CFACT * ((h2 * h2) * H_avg) * s2 + 1e-10f;           \
        if (i < NX - 1) { sDp[i - NX] = Dv; lmax = fmaxf(lmax, Dv); }   \
    }

#define ROLL                                                            \
    zU = zC; zC = z_next; hC = h_next; ZtC = zt_next;                   \
    Dmm = D0m; Dm0 = D00; hw_prev = Hn; zn_prev = Zn;                   \
    { int t_ = p; p = c; c = n; n = t_; }                               \
    ztoff += NXP; smoff += NX; sDp += NX; idx += NX;

__global__ void __launch_bounds__(1024, 1)
k_persist(const float* __restrict__ precip,
          const float* __restrict__ tma_p,
          const float* __restrict__ tmj_p,
          const float* __restrict__ Ztopo,
          const float* __restrict__ mask,
          float* __restrict__ out) {
    extern __shared__ float sm[];
    float* sZt  = sm;                  // 9*NXP : Ztopo rows r0-1 .. r1 (static)
    float* sZr  = sZt  + 9 * NXP;      // 3*NXP : z ring
    float* sHwr = sZr  + 3 * NXP;      // 3*NXP : Hn ring
    float* sZnr = sHwr + 3 * NXP;      // 3*NXP : Zn ring
    float* sDb  = sZnr + 3 * NXP;      // 8*NX  : D band, slot = row-(r0-1)
    float* sSmb = sDb  + 8 * NX;       // 7*NX  : smb band
    __shared__ unsigned wred[32];

    const int i = threadIdx.x;
    const int si = i + 1;
    const int il = (i == 0) ? 0 : i - 1;
    const int nb = gridDim.x;
    const int bid = blockIdx.x;
    const int lane = i & 31, wid = i >> 5;
    const unsigned FULL = 0xFFFFFFFFu;
    const bool iIn = (i > 0) && (i < NX - 1);

    int base = NY / nb, rem = NY % nb;
    const int r0 = bid * base + (bid < rem ? bid : rem);
    const int r1 = r0 + base + (bid < rem ? 1 : 0);
    const int band = r1 - r0;          // 6..7

    const float tma = tma_p[0], tmj = tmj_p[0];
    const float CFACT = (float)(1e-17 * 8927.1 * 8927.1 * 8927.1);

    // ---- one-time init ----
    if (i == 0 || i == NX - 1) {
        int pc = (i == 0) ? 0 : NXP - 1;
        #pragma unroll
        for (int k = 0; k < 9; k++) sZt[k * NXP + pc] = 0.f;
        #pragma unroll
        for (int k = 0; k < 3; k++) {
            sZr[k * NXP + pc] = 0.f; sHwr[k * NXP + pc] = 0.f; sZnr[k * NXP + pc] = 0.f;
        }
    }
    for (int slot = 0; slot < band + 2; slot++) {
        int row = r0 - 1 + slot;
        sZt[slot * NXP + si] = (row >= 0 && row < NY) ? Ztopo[row * NX + i] : 0.0f;
    }
    #pragma unroll
    for (int k = 0; k < 8; k++) sDb[k * NX + i] = 1e-10f;
    __syncthreads();
    for (int j = r0; j < r1; j++) {
        int idx = j * NX + i;
        g_H0[idx] = 0.0f;
        sSmb[(j - r0) * NX + i] =
            smb_of(sZt[(j - r0 + 1) * NXP + si], precip[idx], mask[idx], tma, tmj);
    }
    unsigned target = nb;
    __syncthreads();
    if (i == 0) { red_add_rel(&g_arrive, 1u); while (ld_acq(&g_arrive) < target) __nanosleep(20); }
    __syncthreads();
    target += nb;

    float time = 0.0f, tlast = 0.0f;

    for (int s = 0; s < NSTEPS; s++) {
        const float* Hr = (s & 1) ? g_H1 : g_H0;
        float*       Hw = (s & 1) ? g_H0 : g_H1;

        float maxD = (s == 0) ? 1e-10f : __int_as_float(__ldcg(&g_maxDbits[s]));
        float dt = fminf(2500.0f / (2.7f * maxD), 0.5f);
        if (!(time < 32.0f)) dt = 0.0f;
        float tnew = time + dt;
        bool  upd  = (tnew - tlast) >= 5.0f;
        const bool last = (s == NSTEPS - 1);

        // ---- sweep prologue (row r0) ----
        int idx = r0 * NX + i;
        int c = 0, n = NXP, p = 2 * NXP;
        int ztoff = 2 * NXP;               // sZt slot of row r0+1
        int smoff = 0;
        float* sDp = sDb + NX;             // D slot of row r0
        float zU = (r0 > 0) ? (sZt[si] + __ldcg(&Hr[idx - NX])) : 0.0f;
        float hC  = Hr[idx];
        float ZtC = sZt[NXP + si];
        float zC  = ZtC + hC;
        float Dmm = sDb[il], Dm0 = sDb[i];
        float hw_prev = 0.f, zn_prev = 0.f, lmax = 0.f;
        float h_next, zt_next, z_next, D00, D0m, Hn, Zn;
        sZr[c + si] = zC;
        __syncthreads();

        PHASE12(Hr[idx + NX], iIn && (r0 > 0))     // row r0 (r0+1 < r1 always)
        ROLL

        for (int j = r0 + 1; j < r1 - 1; j++) {    // interior rows: always j-safe
            PHASE12(Hr[idx + NX], iIn)
            PHASE3
            ROLL
        }

        // final row r1-1: halo load from neighbor (or zero past the domain)
        PHASE12((r1 < NY) ? __ldcg(&Hr[idx + NX]) : 0.0f, iIn && (r1 < NY))
        PHASE3

        if (last) {
            for (int j = r0; j < r1; j++) {
                int k = j * NX + i;
                out[k] = Hw[k];
            }
            break;
        }

        // ---- publish band; overlap smb refresh with neighbor skew ----
        __syncthreads();
        if (i == 0) red_add_rel(&g_done[bid * 8], 1u);

        if (upd) {
            for (int j = r0; j < r1; j++) {
                int k = j * NX + i;
                float Hv = Hw[k];
                float Zv = sZt[(j - r0 + 1) * NXP + si] + Hv;
                sSmb[(j - r0) * NX + i] = smb_of(Zv, precip[k], mask[k], tma, tmj);
            }
        }

        if (i == 0 && bid > 0)       { while (ld_acq(&g_done[(bid - 1) * 8]) < (unsigned)(s + 1)) __nanosleep(20); }
        if (i == 32 && bid < nb - 1) { while (ld_acq(&g_done[(bid + 1) * 8]) < (unsigned)(s + 1)) __nanosleep(20); }
        __syncthreads();

        // ---- boundary D rows ----
        if (r0 >= 1 && i < NX - 1) {           // D row r0-1 (needs neighbor row r0-1)
            int ia = (r0 - 1) * NX + i, ib = r0 * NX + i;
            float hA = __ldcg(&Hw[ia]), hAr = __ldcg(&Hw[ia + 1]);
            float hB = Hw[ib],          hBr = Hw[ib + 1];
            float z00 = sZt[si] + hA,        z01 = sZt[si + 1] + hAr;
            float z10 = sZt[NXP + si] + hB,  z11 = sZt[NXP + si + 1] + hBr;
            float H_avg = 0.25f * (((hA + hBr) + hAr) + hB);
            float sx = 0.5f * ((z01 - z00) * INV + (z11 - z10) * INV);
            float sy = 0.5f * ((z10 - z00) * INV + (z11 - z01) * INV);
            float s2 = sx * sx + sy * sy + 1e-10f;
            float h2 = H_avg * H_avg;
            float Dv = CFACT * ((h2 * h2) * H_avg) * s2 + 1e-10f;
            sDb[i] = Dv;
            lmax = fmaxf(lmax, Dv);
        }
        if (r1 <= NY - 1 && i < NX - 1) {      // D row r1-1 (needs neighbor row r1)
            int ia = (r1 - 1) * NX + i, ib = r1 * NX + i;
            int sb = band * NXP;
            float hA = Hw[ia],          hAr = Hw[ia + 1];
            float hB = __ldcg(&Hw[ib]), hBr = __ldcg(&Hw[ib + 1]);
            float z00 = sZt[sb + si] + hA,         z01 = sZt[sb + si + 1] + hAr;
            float z10 = sZt[sb + NXP + si] + hB,   z11 = sZt[sb + NXP + si + 1] + hBr;
            float H_avg = 0.25f * (((hA + hBr) + hAr) + hB);
            float sx = 0.5f * ((z01 - z00) * INV + (z11 - z10) * INV);
            float sy = 0.5f * ((z10 - z00) * INV + (z11 - z01) * INV);
            float s2 = sx * sx + sy * sy + 1e-10f;
            float h2 = H_avg * H_avg;
            float Dv = CFACT * ((h2 * h2) * H_avg) * s2 + 1e-10f;
            sDb[band * NX + i] = Dv;
            lmax = fmaxf(lmax, Dv);
        }

        // ---- max reduce -> slot s+1, then one global barrier ----
        unsigned lb = __reduce_max_sync(FULL, __float_as_uint(lmax));
        if (lane == 0) wred[wid] = lb;
        __syncthreads();
        if (wid == 0) {
            unsigned m = __reduce_max_sync(FULL, wred[lane]);
            if (lane == 0) atomicMax(&g_maxDbits[s + 1], (int)m);
        }
        __syncthreads();
        if (i == 0) { red_add_rel(&g_arrive, 1u); while (ld_acq(&g_arrive) < target) __nanosleep(20); }
        __syncthreads();
        target += nb;

        time = tnew;
        if (upd) tlast = tnew;
    }
}

extern "C" void kernel_launch(void* const* d_in, const int* in_sizes, int n_in,
                              void* d_out, int out_size) {
    const float* precip = (const float*)d_in[0];
    const float* tma_p  = (const float*)d_in[1];
    const float* tmj_p  = (const float*)d_in[2];
    const float* Ztopo  = (const float*)d_in[3];
    const float* mask   = (const float*)d_in[4];
    float* out = (float*)d_out;

    int dev = 0;
    cudaGetDevice(&dev);
    int sms = 0;
    cudaDeviceGetAttribute(&sms, cudaDevAttrMultiProcessorCount, dev);
    if (sms < 1) sms = 1;
    if (sms > 256) sms = 256;

    const int smem_bytes = (18 * NXP + 15 * NX) * (int)sizeof(float);
    cudaFuncSetAttribute(k_persist, cudaFuncAttributeMaxDynamicSharedMemorySize, smem_bytes);

    k_reset<<<1, 1024>>>();
    k_persist<<<sms, 1024, smem_bytes>>>(precip, tma_p, tmj_p, Ztopo, mask, out);
}

// round 8
// speedup vs baseline: 1.4633x; 1.1962x over previous
#include <cuda_runtime.h>
#include <math.h>

#define NY 1024
#define NX 1024
#define SP 1026              // smem row stride (floats), even for float2 alignment
#define NSTEPS 64
#define NPTS (NY*NX)
#define INV 0.02f
#define EPS 1e-10f

__device__ float g_H0[NPTS];
__device__ float g_H1[NPTS];
__device__ int g_maxDbits[NSTEPS];
__device__ unsigned g_arrive;
__device__ unsigned g_done[256 * 8];

static __device__ __forceinline__ unsigned ld_acq(const unsigned* p) {
    unsigned v;
    asm volatile("ld.acquire.gpu.global.u32 %0, [%1];" : "=r"(v) : "l"(p) : "memory");
    return v;
}
static __device__ __forceinline__ void red_add_rel(unsigned* p, unsigned v) {
    asm volatile("red.release.gpu.global.add.u32 [%0], %1;" :: "l"(p), "r"(v) : "memory");
}

static __device__ __forceinline__ float smb_of(float Zs, float precip, float mask,
                                               float tma_low, float tmj_low) {
    float T_ma = tma_low - 0.0065f * Zs;
    float T_mj = tmj_low - 0.0065f * Zs;
    float acc = precip * (T_ma < 0.0f ? 1.0f : 0.0f);
    float abl = 0.5f * fmaxf(T_mj, 0.0f);
    return (acc - abl) * mask;
}

static __device__ __forceinline__ float dcalc(float h00, float h01, float h10, float h11,
                                              float z00, float z01, float z10, float z11,
                                              float CFACT) {
    float H_avg = 0.25f * (((h00 + h11) + h01) + h10);
    float sx = 0.5f * ((z01 - z00) * INV + (z11 - z10) * INV);
    float sy = 0.5f * ((z10 - z00) * INV + (z11 - z01) * INV);
    float s2 = sx * sx + sy * sy + EPS;
    float h2 = H_avg * H_avg;
    return CFACT * ((h2 * h2) * H_avg) * s2 + EPS;
}

static __device__ __forceinline__ float2 ld2(const float* p) { return *(const float2*)p; }
static __device__ __forceinline__ void st2(float* p, float2 v) { *(float2*)p = v; }

__global__ void k_reset() {
    int t = threadIdx.x;
    if (t == 0) g_arrive = 0u;
    if (t < NSTEPS) g_maxDbits[t] = 0;
    for (int k = t; k < 256 * 8; k += blockDim.x) g_done[k] = 0u;
}

// smem slots: sZt[9] | sZ[9] | sHn[7] | sZn[7] | sDb[8] | sSmb[7] = 47 rows * SP
__global__ void __launch_bounds__(512, 1)
k_persist(const float* __restrict__ precip,
          const float* __restrict__ tma_p,
          const float* __restrict__ tmj_p,
          const float* __restrict__ Ztopo,
          const float* __restrict__ mask,
          float* __restrict__ out) {
    extern __shared__ float sm[];
    float* sZt  = sm;              // Ztopo rows r0-1 .. r1 (static)
    float* sZ   = sZt + 9 * SP;    // z = Zt + H(read), rows r0-1 .. r1
    float* sHn  = sZ  + 9 * SP;    // H(read) stage, then Hn, rows r0 .. r1-1
    float* sZn  = sHn + 7 * SP;    // Zn = Zt + Hn
    float* sDb  = sZn + 7 * SP;    // D band, slot = row-(r0-1)
    float* sSmb = sDb + 8 * SP;
    __shared__ unsigned wred[16];

    const int t = threadIdx.x;     // 0..511, owns cols c0, c0+1
    const int c0 = t * 2;
    const int lane = t & 31, wid = t >> 5;
    const int nb = gridDim.x, bid = blockIdx.x;
    const int cl = (c0 == 0) ? 0 : c0 - 1;
    const unsigned FULL = 0xFFFFFFFFu;

    int base = NY / nb, rem = NY % nb;
    const int r0 = bid * base + (bid < rem ? bid : rem);
    const int r1 = r0 + base + (bid < rem ? 1 : 0);
    const int band = r1 - r0;      // <= 7

    const float tma = tma_p[0], tmj = tmj_p[0];
    const float CFACT = (float)(1e-17 * 8927.1 * 8927.1 * 8927.1);
    const bool p0in = (t > 0);
    const bool p1in = (t < 511);

    // ---- one-time init ----
    if (t < 47) { sm[t * SP + 1024] = 0.f; sm[t * SP + 1025] = 0.f; }  // pad cols
    for (int sl = 0; sl <= band + 1; sl++) {
        int row = r0 - 1 + sl;
        float2 zt = make_float2(0.f, 0.f);
        if (row >= 0 && row < NY) zt = ld2(Ztopo + row * NX + c0);
        st2(sZt + sl * SP + c0, zt);
    }
    #pragma unroll
    for (int k = 0; k < 8; k++) st2(sDb + k * SP + c0, make_float2(EPS, EPS));
    __syncthreads();
    for (int j = r0; j < r1; j++) {
        int jb = j - r0;
        st2(g_H0 + j * NX + c0, make_float2(0.f, 0.f));
        float2 zt = ld2(sZt + (jb + 1) * SP + c0);
        float2 pr = ld2(precip + j * NX + c0);
        float2 mk = ld2(mask + j * NX + c0);
        st2(sSmb + jb * SP + c0,
            make_float2(smb_of(zt.x, pr.x, mk.x, tma, tmj),
                        smb_of(zt.y, pr.y, mk.y, tma, tmj)));
    }
    unsigned target = nb;
    __syncthreads();
    if (t == 0) { red_add_rel(&g_arrive, 1u); while (ld_acq(&g_arrive) < target) __nanosleep(20); }
    __syncthreads();
    target += nb;

    float time = 0.0f, tlast = 0.0f;

    for (int s = 0; s < NSTEPS; s++) {
        const float* Hr = (s & 1) ? g_H1 : g_H0;
        float*       Hw = (s & 1) ? g_H0 : g_H1;

        float maxD = (s == 0) ? EPS : __int_as_float(__ldcg(&g_maxDbits[s]));
        float dt = fminf(2500.0f / (2.7f * maxD), 0.5f);
        if (!(time < 32.0f)) dt = 0.0f;
        float tnew = time + dt;
        bool  upd  = (tnew - tlast) >= 5.0f;
        const bool last = (s == NSTEPS - 1);

        // ---- phase Z: stage z rows r0-1..r1 and H(read) for own rows ----
        for (int sl = 0; sl <= band + 1; sl++) {
            int row = r0 - 1 + sl;
            float2 h = make_float2(0.f, 0.f);
            if (row >= 0 && row < NY) {
                const float* p = Hr + row * NX + c0;
                h = (sl == 0 || sl == band + 1) ? __ldcg((const float2*)p)
                                                : ld2(p);
            }
            float2 zt = ld2(sZt + sl * SP + c0);
            st2(sZ + sl * SP + c0, make_float2(zt.x + h.x, zt.y + h.y));
            if (sl >= 1 && sl <= band) st2(sHn + (sl - 1) * SP + c0, h);
        }
        __syncthreads();

        // ---- phase A: H update, rows independent, NO barriers ----
        float lmax = 0.f;
        {
            float2 zU = ld2(sZ + c0);              // row r0-1
            float2 zC = ld2(sZ + SP + c0);         // row r0
            float2 Dup = ld2(sDb + c0);            // D row r0-1
            float  Dup_l = sDb[cl];
            for (int j = r0; j < r1; j++) {
                int jb = j - r0;
                float2 zD = ld2(sZ + (jb + 2) * SP + c0);
                float zLs = sZ[(jb + 1) * SP + cl];
                float zRs = sZ[(jb + 1) * SP + c0 + 2];
                float2 Dcu = ld2(sDb + (jb + 1) * SP + c0);
                float  Dcu_l = sDb[(jb + 1) * SP + cl];
                float2 h2   = ld2(sHn + jb * SP + c0);
                float2 smb2 = ld2(sSmb + jb * SP + c0);
                float2 zt2  = ld2(sZt + (jb + 1) * SP + c0);
                bool jIn = (j > 0) && (j < NY - 1);

                float Hn0 = h2.x;
                if (p0in && jIn) {
                    float qxr = -(0.5f * (Dup.x + Dcu.x)) * (zC.y - zC.x) * INV;
                    float qxl = -(0.5f * (Dup_l + Dcu_l)) * (zC.x - zLs) * INV;
                    float qyd = -(0.5f * (Dcu_l + Dcu.x)) * (zD.x - zC.x) * INV;
                    float qyu = -(0.5f * (Dup_l + Dup.x)) * (zC.x - zU.x) * INV;
                    float dHdt = -((qxr - qxl) * INV + (qyd - qyu) * INV);
                    Hn0 = h2.x + dt * (dHdt + smb2.x);
                }
                float Hn1 = h2.y;
                if (p1in && jIn) {
                    float qxr = -(0.5f * (Dup.y + Dcu.y)) * (zRs - zC.y) * INV;
                    float qxl = -(0.5f * (Dup.x + Dcu.x)) * (zC.y - zC.x) * INV;
                    float qyd = -(0.5f * (Dcu.x + Dcu.y)) * (zD.y - zC.y) * INV;
                    float qyu = -(0.5f * (Dup.x + Dup.y)) * (zC.y - zU.y) * INV;
                    float dHdt = -((qxr - qxl) * INV + (qyd - qyu) * INV);
                    Hn1 = h2.y + dt * (dHdt + smb2.y);
                }
                Hn0 = fmaxf(Hn0, 0.f);
                Hn1 = fmaxf(Hn1, 0.f);
                float2 Hn2 = make_float2(Hn0, Hn1);
                st2(Hw + j * NX + c0, Hn2);
                st2(sHn + jb * SP + c0, Hn2);
                st2(sZn + jb * SP + c0, make_float2(zt2.x + Hn0, zt2.y + Hn1));
                if (last) st2(out + j * NX + c0, Hn2);
                zU = zC; zC = zD; Dup = Dcu; Dup_l = Dcu_l;
            }
        }
        __syncthreads();
        if (last) break;
        if (t == 0) red_add_rel(&g_done[bid * 8], 1u);

        // ---- phase B: interior D rows r0..r1-2 from staged Hn/Zn ----
        {
            float2 ha = ld2(sHn + c0); float haR = sHn[c0 + 2];
            float2 za = ld2(sZn + c0); float zaR = sZn[c0 + 2];
            for (int j = r0; j < r1 - 1; j++) {
                int jb = j - r0;
                float2 hb = ld2(sHn + (jb + 1) * SP + c0); float hbR = sHn[(jb + 1) * SP + c0 + 2];
                float2 zb = ld2(sZn + (jb + 1) * SP + c0); float zbR = sZn[(jb + 1) * SP + c0 + 2];
                float D0 = dcalc(ha.x, ha.y, hb.x, hb.y, za.x, za.y, zb.x, zb.y, CFACT);
                float D1 = dcalc(ha.y, haR, hb.y, hbR, za.y, zaR, zb.y, zbR, CFACT);
                st2(sDb + (jb + 1) * SP + c0, make_float2(D0, D1));
                lmax = fmaxf(lmax, D0);
                if (p1in) lmax = fmaxf(lmax, D1);
                ha = hb; haR = hbR; za = zb; zaR = zbR;
            }
        }

        // ---- smb refresh (rare), overlapped with neighbor skew ----
        if (upd) {
            for (int j = r0; j < r1; j++) {
                int jb = j - r0;
                float2 Hv = ld2(sHn + jb * SP + c0);
                float2 zt2 = ld2(sZt + (jb + 1) * SP + c0);
                float2 pr = ld2(precip + j * NX + c0);
                float2 mk = ld2(mask + j * NX + c0);
                st2(sSmb + jb * SP + c0,
                    make_float2(smb_of(zt2.x + Hv.x, pr.x, mk.x, tma, tmj),
                                smb_of(zt2.y + Hv.y, pr.y, mk.y, tma, tmj)));
            }
        }

        // ---- wait neighbors, then boundary D rows ----
        if (t == 0 && bid > 0)        { while (ld_acq(&g_done[(bid - 1) * 8]) < (unsigned)(s + 1)) __nanosleep(20); }
        if (t == 32 && bid < nb - 1)  { while (ld_acq(&g_done[(bid + 1) * 8]) < (unsigned)(s + 1)) __nanosleep(20); }
        __syncthreads();

        if (r0 >= 1) {                 // D row r0-1: rows (r0-1)=neighbor, r0=own
            const float* pa = Hw + (r0 - 1) * NX + c0;
            float2 ha = __ldcg((const float2*)pa);
            float  haR = p1in ? __ldcg(pa + 2) : 0.f;
            float2 zta = ld2(sZt + c0); float ztaR = sZt[c0 + 2];
            float2 za = make_float2(zta.x + ha.x, zta.y + ha.y);
            float  zaR = ztaR + haR;
            float2 hb = ld2(sHn + c0); float hbR = sHn[c0 + 2];
            float2 zb = ld2(sZn + c0); float zbR = sZn[c0 + 2];
            float D0 = dcalc(ha.x, ha.y, hb.x, hb.y, za.x, za.y, zb.x, zb.y, CFACT);
            float D1 = dcalc(ha.y, haR, hb.y, hbR, za.y, zaR, zb.y, zbR, CFACT);
            st2(sDb + c0, make_float2(D0, D1));
            lmax = fmaxf(lmax, D0);
            if (p1in) lmax = fmaxf(lmax, D1);
        }
        if (r1 <= NY - 1) {            // D row r1-1: rows (r1-1)=own, r1=neighbor
            float2 ha = ld2(sHn + (band - 1) * SP + c0); float haR = sHn[(band - 1) * SP + c0 + 2];
            float2 za = ld2(sZn + (band - 1) * SP + c0); float zaR = sZn[(band - 1) * SP + c0 + 2];
            const float* pb = Hw + r1 * NX + c0;
            float2 hb = __ldcg((const float2*)pb);
            float  hbR = p1in ? __ldcg(pb + 2) : 0.f;
            float2 ztb = ld2(sZt + (band + 1) * SP + c0); float ztbR = sZt[(band + 1) * SP + c0 + 2];
            float2 zb = make_float2(ztb.x + hb.x, ztb.y + hb.y);
            float  zbR = ztbR + hbR;
            float D0 = dcalc(ha.x, ha.y, hb.x, hb.y, za.x, za.y, zb.x, zb.y, CFACT);
            float D1 = dcalc(ha.y, haR, hb.y, hbR, za.y, zaR, zb.y, zbR, CFACT);
            st2(sDb + band * SP + c0, make_float2(D0, D1));
            lmax = fmaxf(lmax, D0);
            if (p1in) lmax = fmaxf(lmax, D1);
        }

        // ---- max reduce -> slot s+1, one global barrier ----
        unsigned lb = __reduce_max_sync(FULL, __float_as_uint(lmax));
        if (lane == 0) wred[wid] = lb;
        __syncthreads();
        if (wid == 0) {
            unsigned v = (lane < 16) ? wred[lane] : 0u;
            unsigned m = __reduce_max_sync(FULL, v);
            if (lane == 0) atomicMax(&g_maxDbits[s + 1], (int)m);
        }
        __syncthreads();
        if (t == 0) { red_add_rel(&g_arrive, 1u); while (ld_acq(&g_arrive) < target) __nanosleep(20); }
        __syncthreads();
        target += nb;

        time = tnew;
        if (upd) tlast = tnew;
    }
}

extern "C" void kernel_launch(void* const* d_in, const int* in_sizes, int n_in,
                              void* d_out, int out_size) {
    const float* precip = (const float*)d_in[0];
    const float* tma_p  = (const float*)d_in[1];
    const float* tmj_p  = (const float*)d_in[2];
    const float* Ztopo  = (const float*)d_in[3];
    const float* mask   = (const float*)d_in[4];
    float* out = (float*)d_out;

    int dev = 0;
    cudaGetDevice(&dev);
    int sms = 0;
    cudaDeviceGetAttribute(&sms, cudaDevAttrMultiProcessorCount, dev);
    if (sms < 1) sms = 1;
    if (sms > 256) sms = 256;

    const int smem_bytes = 47 * SP * (int)sizeof(float);
    cudaFuncSetAttribute(k_persist, cudaFuncAttributeMaxDynamicSharedMemorySize, smem_bytes);

    k_reset<<<1, 1024>>>();
    k_persist<<<sms, 512, smem_bytes>>>(precip, tma_p, tmj_p, Ztopo, mask, out);
}